// round 15
// baseline (speedup 1.0000x reference)
#include <cuda_runtime.h>
#include <cuda_fp16.h>
#include <cstdint>

// Problem constants (fixed by the reference)
#define Bn   4
#define Cn   128
#define HWn  16384      // 128*128
#define Pn   4096
#define Vn   32
#define PT   8          // points per block (1 warp per point)

// Split-plane fp16 scratch: plane A = channels 0..63, plane B = channels
// 64..127, each [B][HW][64] halves (128B rows).
#define PLANE_HALF2 ((size_t)Bn * HWn * 32)   // half2 units per plane
#define PLANE_UINT2 ((size_t)Bn * HWn * 16)   // uint2 units per plane
__device__ __align__(16) __half g_xt[(size_t)2 * Bn * HWn * 64];

// Gather load: read-only, no L1 allocation (best measured variant).
__device__ __forceinline__ uint2 ldg_na(const uint2* p)
{
    uint2 r;
    asm volatile("ld.global.nc.L1::no_allocate.v2.u32 {%0,%1}, [%2];"
                 : "=r"(r.x), "=r"(r.y) : "l"(p));
    return r;
}

// ---------------------------------------------------------------------------
// Kernel 1 (PDL primary): transpose + downconvert x [B,C,HW] -> split planes.
// Each block triggers programmatic completion after its stores; the gather
// kernel's pre-sync prologue overlaps with the transpose tail.
// ---------------------------------------------------------------------------
__global__ __launch_bounds__(256) void transpose_fp16_kernel(const float* __restrict__ x)
{
    __shared__ float tile[64][33];

    const int b   = blockIdx.z;
    const int hw0 = blockIdx.x * 32;
    const int c0  = blockIdx.y * 64;     // 0 or 64 -> plane select
    const int tx  = threadIdx.x;   // 0..31
    const int ty  = threadIdx.y;   // 0..7

    #pragma unroll
    for (int j = 0; j < 8; j++) {
        const int cl = ty + j * 8;
        tile[cl][tx] = x[((size_t)b * Cn + c0 + cl) * HWn + hw0 + tx];
    }
    __syncthreads();

    const int t = ty * 32 + tx;
    __half2* xt2 = reinterpret_cast<__half2*>(g_xt) + (c0 >= 64 ? PLANE_HALF2 : 0);
    #pragma unroll
    for (int j = 0; j < 4; j++) {
        const int idx  = j * 256 + t;          // 0..1023
        const int hw_l = idx >> 5;             // 0..31
        const int c2   = idx & 31;             // half2 index within 64-ch row
        const float f0 = tile[c2 * 2][hw_l];
        const float f1 = tile[c2 * 2 + 1][hw_l];
        xt2[((size_t)b * HWn + hw0 + hw_l) * 32 + c2] = __floats2half2_rn(f0, f1);
    }

    cudaTriggerProgrammaticLaunchCompletion();
}

// ---------------------------------------------------------------------------
// Kernel 2 (PDL secondary): gather + vote accumulate. ONE WARP PER POINT.
// Stages vote indices/weights (reads only inds/vote tables), THEN waits for
// the transpose grid via cudaGridDependencySynchronize, then gathers.
// Body = round-12 best (16.2us).
// ---------------------------------------------------------------------------
__global__ __launch_bounds__(256, 8) void gather_kernel(
    const int*   __restrict__ vote_index,   // [32768, 32]
    const float* __restrict__ vote_weight,  // [32768, 32]
    const int*   __restrict__ inds,         // [B, P] int32
    float*       __restrict__ out)          // [B, C, P]
{
    __shared__ uint2 s_iw[PT][Vn];   // {hw * 16 (uint2 row offset), half2(w,w)}
    __shared__ float s_out[PT][132];

    const int b    = blockIdx.y;
    const int p0   = blockIdx.x * PT;
    const int t    = threadIdx.x;
    const int warp = t >> 5;
    const int lane = t & 31;

    // ---- Pre-sync prologue: does NOT touch g_xt -----------------------
    {
        const int sph = inds[(size_t)b * Pn + p0 + warp];   // warp-uniform
        const int hw  = vote_index[(size_t)sph * Vn + lane];
        const float w = vote_weight[(size_t)sph * Vn + lane];
        const __half2 w2 = __float2half2_rn(w);
        s_iw[warp][lane] = make_uint2((unsigned)hw * 16u,
                                      *reinterpret_cast<const unsigned*>(&w2));
    }
    __syncthreads();

    // Wait until the transpose grid's writes to g_xt are visible.
    cudaGridDependencySynchronize();

    // Per-lane base: plane select + batch base + lane slot within 16-uint2 row.
    const uint2* xt = reinterpret_cast<const uint2*>(g_xt)
                    + (lane >= 16 ? PLANE_UINT2 : 0)
                    + (size_t)b * HWn * 16
                    + (lane & 15);

    float2 accA = make_float2(0.f, 0.f);
    float2 accB = make_float2(0.f, 0.f);

    #pragma unroll
    for (int g = 0; g < Vn / 4; g++) {           // 8 groups of 4 votes
        const uint2 iw0 = s_iw[warp][g * 4 + 0];
        const uint2 iw1 = s_iw[warp][g * 4 + 1];
        const uint2 iw2 = s_iw[warp][g * 4 + 2];
        const uint2 iw3 = s_iw[warp][g * 4 + 3];
        const uint2 r0 = ldg_na(xt + iw0.x);
        const uint2 r1 = ldg_na(xt + iw1.x);
        const uint2 r2 = ldg_na(xt + iw2.x);
        const uint2 r3 = ldg_na(xt + iw3.x);

        __half2 h0 = __float2half2_rn(0.f);
        __half2 h1 = __float2half2_rn(0.f);
        h0 = __hfma2(*reinterpret_cast<const __half2*>(&r0.x),
                     *reinterpret_cast<const __half2*>(&iw0.y), h0);
        h1 = __hfma2(*reinterpret_cast<const __half2*>(&r0.y),
                     *reinterpret_cast<const __half2*>(&iw0.y), h1);
        h0 = __hfma2(*reinterpret_cast<const __half2*>(&r1.x),
                     *reinterpret_cast<const __half2*>(&iw1.y), h0);
        h1 = __hfma2(*reinterpret_cast<const __half2*>(&r1.y),
                     *reinterpret_cast<const __half2*>(&iw1.y), h1);
        h0 = __hfma2(*reinterpret_cast<const __half2*>(&r2.x),
                     *reinterpret_cast<const __half2*>(&iw2.y), h0);
        h1 = __hfma2(*reinterpret_cast<const __half2*>(&r2.y),
                     *reinterpret_cast<const __half2*>(&iw2.y), h1);
        h0 = __hfma2(*reinterpret_cast<const __half2*>(&r3.x),
                     *reinterpret_cast<const __half2*>(&iw3.y), h0);
        h1 = __hfma2(*reinterpret_cast<const __half2*>(&r3.y),
                     *reinterpret_cast<const __half2*>(&iw3.y), h1);

        const float2 f0 = __half22float2(h0);
        const float2 f1 = __half22float2(h1);
        accA.x += f0.x; accA.y += f0.y;
        accB.x += f1.x; accB.y += f1.y;
    }

    // Lane l holds channels 4l..4l+3 (plane split preserves this mapping).
    *reinterpret_cast<float4*>(&s_out[warp][lane * 4]) =
        make_float4(accA.x, accA.y, accB.x, accB.y);
    __syncthreads();

    // Write out [C][PT] tile: 8 consecutive p per c row.
    #pragma unroll
    for (int i = t; i < Cn * PT; i += 256) {
        const int c  = i >> 3;   // i / PT
        const int pl = i & 7;    // i % PT
        out[((size_t)b * Cn + c) * Pn + p0 + pl] = s_out[pl][c];
    }
}

// ---------------------------------------------------------------------------
// Launch: transpose, then gather with programmatic dependent launch so the
// gather's prologue overlaps the transpose tail. Allocation-free,
// graph-capturable (PDL attributes are supported in graphs).
// ---------------------------------------------------------------------------
extern "C" void kernel_launch(void* const* d_in, const int* in_sizes, int n_in,
                              void* d_out, int out_size)
{
    const float* x           = (const float*)d_in[0];   // [4,128,128,128]
    const int*   vote_index  = (const int*)d_in[1];     // [32768,32]
    const float* vote_weight = (const float*)d_in[2];   // [32768,32]
    const int*   inds        = (const int*)d_in[3];     // [4,4096] int32
    float*       out         = (float*)d_out;           // [4,128,4096]

    {
        dim3 grid(HWn / 32, Cn / 64, Bn);   // (512, 2, 4)
        dim3 block(32, 8);
        transpose_fp16_kernel<<<grid, block>>>(x);
    }
    {
        cudaLaunchConfig_t cfg = {};
        cfg.gridDim  = dim3(Pn / PT, Bn, 1);   // (512, 4) = 2048 blocks
        cfg.blockDim = dim3(256, 1, 1);
        cfg.dynamicSmemBytes = 0;
        cfg.stream = (cudaStream_t)0;          // same (captured) default stream

        cudaLaunchAttribute attr[1];
        attr[0].id = cudaLaunchAttributeProgrammaticStreamSerialization;
        attr[0].val.programmaticStreamSerializationAllowed = 1;
        cfg.attrs = attr;
        cfg.numAttrs = 1;

        cudaLaunchKernelEx(&cfg, gather_kernel, vote_index, vote_weight, inds, out);
    }
}